// round 13
// baseline (speedup 1.0000x reference)
#include <cuda_runtime.h>
#include <cuda_fp16.h>
#include <math.h>
#include <stdint.h>

#define MM 32768
#define DD 1152
#define HH 4608

// ---- scratch (__device__ globals; no allocation allowed) ----
__device__ float    g_sx[MM];
__device__ float    g_s2[MM];
__device__ unsigned g_amax[MM];
__device__ __half   g_aq1[(size_t)MM * DD];
__device__ __half   g_aq2[(size_t)MM * HH];
__device__ float    g_h  [(size_t)MM * HH];
__device__ __half   g_w1hi[(size_t)HH * DD], g_w1lo[(size_t)HH * DD];
__device__ __half   g_w2hi[(size_t)HH * DD];

__device__ __forceinline__ uint32_t swz(uint32_t b) {
    // 128B-row XOR swizzle: bits[6:4] ^= row%8 (row stride = 128B)
    return b ^ (((b >> 7) & 7u) << 4);
}
__device__ __forceinline__ uint32_t smem_u32(const void* p) {
    uint32_t a;
    asm("{ .reg .u64 t; cvta.to.shared.u64 t, %1; cvt.u32.u64 %0, t; }" : "=r"(a) : "l"(p));
    return a;
}
__device__ __forceinline__ void ldm4(uint32_t* r, uint32_t addr) {
    asm volatile("ldmatrix.sync.aligned.m8n8.x4.shared.b16 {%0,%1,%2,%3}, [%4];"
        : "=r"(r[0]), "=r"(r[1]), "=r"(r[2]), "=r"(r[3]) : "r"(addr));
}
__device__ __forceinline__ void mma16816(float* d, const uint32_t* a, uint32_t b0, uint32_t b1) {
    asm volatile("mma.sync.aligned.m16n8k16.row.col.f32.f16.f16.f32 "
        "{%0,%1,%2,%3}, {%4,%5,%6,%7}, {%8,%9}, {%0,%1,%2,%3};"
        : "+f"(d[0]), "+f"(d[1]), "+f"(d[2]), "+f"(d[3])
        : "r"(a[0]), "r"(a[1]), "r"(a[2]), "r"(a[3]), "r"(b0), "r"(b1));
}
__device__ __forceinline__ void cpa16(uint32_t dst, const void* src) {
    asm volatile("cp.async.cg.shared.global [%0], [%1], 16;" :: "r"(dst), "l"(src));
}
#define CP_COMMIT() asm volatile("cp.async.commit_group;" ::: "memory")
#define CP_WAIT1()  asm volatile("cp.async.wait_group 1;" ::: "memory")

__device__ __forceinline__ float gelu_exact(float v) {
    return 0.5f * v * (1.0f + erff(v * 0.70710678118654752f));
}

// ---------------------------------------------------------------------------
__global__ void pack_w1(const float* __restrict__ W, size_t total,
                        __half* __restrict__ hi, __half* __restrict__ lo) {
    for (size_t i = (size_t)blockIdx.x * blockDim.x + threadIdx.x; i < total;
         i += (size_t)gridDim.x * blockDim.x) {
        float w = W[i];
        __half h = __float2half_rn(w);
        hi[i] = h;
        lo[i] = __float2half_rn(w - __half2float(h));
    }
}
__global__ void pack_w2(const float* __restrict__ W, size_t total,
                        __half* __restrict__ hi) {
    for (size_t i = (size_t)blockIdx.x * blockDim.x + threadIdx.x; i < total;
         i += (size_t)gridDim.x * blockDim.x)
        hi[i] = __float2half_rn(W[i]);
}

__global__ void fq_input(const float* __restrict__ x, const int* __restrict__ ridx) {
    int m = blockIdx.x;
    const float* xr = x + (size_t)m * DD;
    __shared__ float red[4];
    float amax = 0.f;
    for (int d = threadIdx.x; d < DD; d += 128) amax = fmaxf(amax, fabsf(xr[ridx[d]]));
    #pragma unroll
    for (int o = 16; o; o >>= 1) amax = fmaxf(amax, __shfl_xor_sync(~0u, amax, o));
    if ((threadIdx.x & 31) == 0) red[threadIdx.x >> 5] = amax;
    __syncthreads();
    amax = fmaxf(fmaxf(red[0], red[1]), fmaxf(red[2], red[3]));
    float s = fmaxf(amax / 127.0f, 1e-8f);
    if (threadIdx.x == 0) g_sx[m] = s;
    __half* orow = g_aq1 + (size_t)m * DD;
    for (int p = threadIdx.x; p < DD / 2; p += 128) {
        float q0 = fminf(fmaxf(rintf(xr[ridx[2*p]]   / s), -128.f), 127.f);
        float q1 = fminf(fmaxf(rintf(xr[ridx[2*p+1]] / s), -128.f), 127.f);
        *(__half2*)(orow + 2*p) = __floats2half2_rn(q0, q1);
    }
}

__global__ void quantize_h() {
    int m = blockIdx.x;
    float s = fmaxf(__uint_as_float(g_amax[m]) / 127.0f, 1e-8f);
    if (threadIdx.x == 0) g_s2[m] = s;
    const float* hr = g_h + (size_t)m * HH;
    __half* orow = g_aq2 + (size_t)m * HH;
    for (int p = threadIdx.x; p < HH / 2; p += 256) {
        float2 v = *(const float2*)(hr + 2*p);
        float q0 = fminf(fmaxf(rintf(v.x / s), -128.f), 127.f);
        float q1 = fminf(fmaxf(rintf(v.y / s), -128.f), 127.f);
        *(__half2*)(orow + 2*p) = __floats2half2_rn(q0, q1);
    }
}

// ---------------------------------------------------------------------------
// GEMM1 (hi+lo, GELU+absmax): CTA 128x128, BK=64, 2-stage cp.async,
// 512 threads = 16 warps (4m x 4n), warp tile 32x32 -> acc 32 regs;
// __launch_bounds__(512, 2) caps regs at 64 -> 2 CTAs/SM -> 32 warps (50% occ).
// ---------------------------------------------------------------------------
__global__ void __launch_bounds__(512, 2)
gemm1_mma(const __half* __restrict__ A, const __half* __restrict__ Bh,
          const __half* __restrict__ Bl, const float* __restrict__ bias,
          const float* __restrict__ rowscale, float* __restrict__ C,
          int ldc, int K, unsigned* __restrict__ amaxU)
{
    constexpr uint32_t STAGE = 49152u;   // A16K | Bh16K | Bl16K
    extern __shared__ char smem[];
    const uint32_t sb = smem_u32(smem);
    const int tid = threadIdx.x;
    const int wid = tid >> 5, lane = tid & 31;
    const int wm = wid & 3, wn = wid >> 2;     // 4 (m) x 4 (n)
    const int bm = blockIdx.y * 128, bn = blockIdx.x * 128;
    const int nk = K >> 6;

    const int lr = lane & 15, lc = lane >> 4;
    uint32_t aoff[2], boff[2];
    #pragma unroll
    for (int mt = 0; mt < 2; mt++)
        aoff[mt] = swz((uint32_t)((wm * 32 + mt * 16 + lr) * 128 + lc * 16));
    #pragma unroll
    for (int g = 0; g < 2; g++)
        boff[g] = swz((uint32_t)((wn * 32 + g * 16 + lr) * 128 + lc * 16));

    float acc[2][4][4];
    #pragma unroll
    for (int i = 0; i < 2; i++)
        #pragma unroll
        for (int j = 0; j < 4; j++)
            #pragma unroll
            for (int l = 0; l < 4; l++) acc[i][j][l] = 0.f;

    // Fill: 512 threads, 6 chunks each; slab i lies in region i>>1,
    // rows (tid>>3) + 64*(i&1). swz(b+8192)=swz(b)+8192 (row%8 unchanged).
    const uint32_t fd0 = swz((uint32_t)((tid >> 3) * 128 + (tid & 7) * 16));
    const size_t   fs0 = (size_t)(tid >> 3) * K + (tid & 7) * 8;
    const __half* fA  = A  + (size_t)bm * K + fs0;
    const __half* fBh = Bh + (size_t)bn * K + fs0;
    const __half* fBl = Bl + (size_t)bn * K + fs0;
    const size_t rstep = (size_t)64 * K;

    auto fill = [&](int s, int k0) {
        uint32_t st = sb + (uint32_t)s * STAGE + fd0;
        cpa16(st,                    fA  + k0);
        cpa16(st + 8192u,            fA  + rstep + k0);
        cpa16(st + 16384u,           fBh + k0);
        cpa16(st + 16384u + 8192u,   fBh + rstep + k0);
        cpa16(st + 32768u,           fBl + k0);
        cpa16(st + 32768u + 8192u,   fBl + rstep + k0);
    };

    fill(0, 0);  CP_COMMIT();
    if (nk > 1) fill(1, 64);
    CP_COMMIT();

    for (int ks = 0; ks < nk; ks++) {
        CP_WAIT1();
        __syncthreads();
        const uint32_t st = sb + (uint32_t)(ks & 1) * STAGE;

        #pragma unroll
        for (int kk = 0; kk < 4; kk++) {
            const uint32_t kx = (uint32_t)(kk * 32);
            uint32_t a[2][4], b[2][4];
            #pragma unroll
            for (int mt = 0; mt < 2; mt++) ldm4(a[mt], st + (aoff[mt] ^ kx));
            #pragma unroll
            for (int g = 0; g < 2; g++) ldm4(b[g], st + 16384u + (boff[g] ^ kx));
            #pragma unroll
            for (int mt = 0; mt < 2; mt++)
                #pragma unroll
                for (int g = 0; g < 2; g++) {
                    mma16816(acc[mt][2*g],   a[mt], b[g][0], b[g][2]);
                    mma16816(acc[mt][2*g+1], a[mt], b[g][1], b[g][3]);
                }
            #pragma unroll
            for (int g = 0; g < 2; g++) ldm4(b[g], st + 32768u + (boff[g] ^ kx));
            #pragma unroll
            for (int mt = 0; mt < 2; mt++)
                #pragma unroll
                for (int g = 0; g < 2; g++) {
                    mma16816(acc[mt][2*g],   a[mt], b[g][0], b[g][2]);
                    mma16816(acc[mt][2*g+1], a[mt], b[g][1], b[g][3]);
                }
        }

        __syncthreads();
        if (ks + 2 < nk) fill(ks & 1, (ks + 2) * 64);
        CP_COMMIT();
    }

    // ---- epilogue: bias + GELU + store + row absmax ----
    const int q = lane >> 2, c2 = (lane & 3) * 2;
    #pragma unroll
    for (int mt = 0; mt < 2; mt++) {
        int r0 = bm + wm * 32 + mt * 16 + q;
        float rs0 = rowscale[r0], rs1 = rowscale[r0 + 8];
        float mx0 = 0.f, mx1 = 0.f;
        #pragma unroll
        for (int nt = 0; nt < 4; nt++) {
            int col = bn + wn * 32 + nt * 8 + c2;
            float2 bb = *(const float2*)(bias + col);
            float v0 = gelu_exact(acc[mt][nt][0] * rs0 + bb.x);
            float v1 = gelu_exact(acc[mt][nt][1] * rs0 + bb.y);
            float v2 = gelu_exact(acc[mt][nt][2] * rs1 + bb.x);
            float v3 = gelu_exact(acc[mt][nt][3] * rs1 + bb.y);
            mx0 = fmaxf(mx0, fmaxf(fabsf(v0), fabsf(v1)));
            mx1 = fmaxf(mx1, fmaxf(fabsf(v2), fabsf(v3)));
            float2 o0 = {v0, v1}, o1 = {v2, v3};
            *(float2*)(C + (size_t)r0 * ldc + col) = o0;
            *(float2*)(C + (size_t)(r0 + 8) * ldc + col) = o1;
        }
        mx0 = fmaxf(mx0, __shfl_xor_sync(~0u, mx0, 1));
        mx0 = fmaxf(mx0, __shfl_xor_sync(~0u, mx0, 2));
        mx1 = fmaxf(mx1, __shfl_xor_sync(~0u, mx1, 1));
        mx1 = fmaxf(mx1, __shfl_xor_sync(~0u, mx1, 2));
        if ((lane & 3) == 0) {
            atomicMax(amaxU + r0,     __float_as_uint(mx0));
            atomicMax(amaxU + r0 + 8, __float_as_uint(mx1));
        }
    }
}

// ---------------------------------------------------------------------------
// GEMM2 (hi only): CTA 128x128, BK=64, 3-stage ring (single barrier/k-step),
// 512 threads = 16 warps (4m x 4n), warp tile 32x32, 2 CTAs/SM (50% occ).
// ---------------------------------------------------------------------------
__global__ void __launch_bounds__(512, 2)
gemm2_mma(const __half* __restrict__ A, const __half* __restrict__ Bh,
          const float* __restrict__ bias, const float* __restrict__ rowscale,
          float* __restrict__ C, int ldc, int K)
{
    constexpr uint32_t STAGE = 32768u;   // A16K | Bh16K
    extern __shared__ char smem[];
    const uint32_t sb = smem_u32(smem);
    const int tid = threadIdx.x;
    const int wid = tid >> 5, lane = tid & 31;
    const int wm = wid & 3, wn = wid >> 2;
    const int bm = blockIdx.y * 128, bn = blockIdx.x * 128;
    const int nk = K >> 6;

    const int lr = lane & 15, lc = lane >> 4;
    uint32_t aoff[2], boff[2];
    #pragma unroll
    for (int mt = 0; mt < 2; mt++)
        aoff[mt] = swz((uint32_t)((wm * 32 + mt * 16 + lr) * 128 + lc * 16));
    #pragma unroll
    for (int g = 0; g < 2; g++)
        boff[g] = 16384u + swz((uint32_t)((wn * 32 + g * 16 + lr) * 128 + lc * 16));

    float acc[2][4][4];
    #pragma unroll
    for (int i = 0; i < 2; i++)
        #pragma unroll
        for (int j = 0; j < 4; j++)
            #pragma unroll
            for (int l = 0; l < 4; l++) acc[i][j][l] = 0.f;

    // Fill: 512 threads, 4 chunks each (A rows 0-63/64-127, B rows 0-63/64-127).
    const uint32_t fd0 = swz((uint32_t)((tid >> 3) * 128 + (tid & 7) * 16));
    const size_t   fs0 = (size_t)(tid >> 3) * K + (tid & 7) * 8;
    const __half* fA  = A  + (size_t)bm * K + fs0;
    const __half* fBh = Bh + (size_t)bn * K + fs0;
    const size_t rstep = (size_t)64 * K;

    auto fill = [&](int s, int k0) {
        uint32_t st = sb + (uint32_t)s * STAGE + fd0;
        cpa16(st,                  fA  + k0);
        cpa16(st + 8192u,          fA  + rstep + k0);
        cpa16(st + 16384u,         fBh + k0);
        cpa16(st + 16384u + 8192u, fBh + rstep + k0);
    };

    fill(0, 0);  CP_COMMIT();
    fill(1, 64); CP_COMMIT();

    int stage = 0;
    for (int ks = 0; ks < nk; ks++) {
        CP_WAIT1();
        __syncthreads();
        if (ks + 2 < nk) {
            int ts = stage + 2; if (ts >= 3) ts -= 3;
            fill(ts, (ks + 2) * 64);
        }
        CP_COMMIT();

        const uint32_t st = sb + (uint32_t)stage * STAGE;
        #pragma unroll
        for (int kk = 0; kk < 4; kk++) {
            const uint32_t kx = (uint32_t)(kk * 32);
            uint32_t a[2][4], b[2][4];
            #pragma unroll
            for (int mt = 0; mt < 2; mt++) ldm4(a[mt], st + (aoff[mt] ^ kx));
            #pragma unroll
            for (int g = 0; g < 2; g++) ldm4(b[g], st + (boff[g] ^ kx));
            #pragma unroll
            for (int mt = 0; mt < 2; mt++)
                #pragma unroll
                for (int g = 0; g < 2; g++) {
                    mma16816(acc[mt][2*g],   a[mt], b[g][0], b[g][2]);
                    mma16816(acc[mt][2*g+1], a[mt], b[g][1], b[g][3]);
                }
        }
        if (++stage == 3) stage = 0;
    }

    const int q = lane >> 2, c2 = (lane & 3) * 2;
    #pragma unroll
    for (int mt = 0; mt < 2; mt++) {
        int r0 = bm + wm * 32 + mt * 16 + q;
        float rs0 = rowscale[r0], rs1 = rowscale[r0 + 8];
        #pragma unroll
        for (int nt = 0; nt < 4; nt++) {
            int col = bn + wn * 32 + nt * 8 + c2;
            float2 bb = *(const float2*)(bias + col);
            float2 o0 = {acc[mt][nt][0] * rs0 + bb.x, acc[mt][nt][1] * rs0 + bb.y};
            float2 o1 = {acc[mt][nt][2] * rs1 + bb.x, acc[mt][nt][3] * rs1 + bb.y};
            *(float2*)(C + (size_t)r0 * ldc + col) = o0;
            *(float2*)(C + (size_t)(r0 + 8) * ldc + col) = o1;
        }
    }
}

// ---------------------------------------------------------------------------
extern "C" void kernel_launch(void* const* d_in, const int* in_sizes, int n_in,
                              void* d_out, int out_size) {
    const float* x   = (const float*)d_in[0];
    const int*   idx = (const int*)d_in[1];
    const float* W1  = (const float*)d_in[2];
    const float* b1  = (const float*)d_in[3];
    const float* W2  = (const float*)d_in[4];
    const float* b2  = (const float*)d_in[5];
    float* out = (float*)d_out;

    void *aq1, *aq2, *hptr, *w1h, *w1l, *w2h, *sx, *s2, *am;
    cudaGetSymbolAddress(&aq1, g_aq1);  cudaGetSymbolAddress(&aq2, g_aq2);
    cudaGetSymbolAddress(&hptr, g_h);
    cudaGetSymbolAddress(&w1h, g_w1hi); cudaGetSymbolAddress(&w1l, g_w1lo);
    cudaGetSymbolAddress(&w2h, g_w2hi);
    cudaGetSymbolAddress(&sx, g_sx);    cudaGetSymbolAddress(&s2, g_s2);
    cudaGetSymbolAddress(&am, g_amax);

    const int SMEM1 = 2 * 49152;   // 96KB -> 2 CTAs/SM
    const int SMEM2 = 3 * 32768;   // 96KB -> 2 CTAs/SM
    cudaFuncSetAttribute((const void*)gemm1_mma, cudaFuncAttributeMaxDynamicSharedMemorySize, SMEM1);
    cudaFuncSetAttribute((const void*)gemm2_mma, cudaFuncAttributeMaxDynamicSharedMemorySize, SMEM2);

    pack_w1<<<2048, 256>>>(W1, (size_t)HH * DD, (__half*)w1h, (__half*)w1l);
    pack_w2<<<2048, 256>>>(W2, (size_t)DD * HH, (__half*)w2h);
    cudaMemsetAsync(am, 0, MM * sizeof(unsigned));
    fq_input<<<MM, 128>>>(x, idx);

    gemm1_mma<<<dim3(HH / 128, MM / 128), 512, SMEM1>>>(
        (const __half*)aq1, (const __half*)w1h, (const __half*)w1l,
        b1, (const float*)sx, (float*)hptr, HH, DD, (unsigned*)am);

    quantize_h<<<MM, 256>>>();

    gemm2_mma<<<dim3(DD / 128, MM / 128), 512, SMEM2>>>(
        (const __half*)aq2, (const __half*)w2h,
        b2, (const float*)s2, out, DD, HH);
}

// round 15
// speedup vs baseline: 1.0825x; 1.0825x over previous
#include <cuda_runtime.h>
#include <cuda_fp16.h>
#include <math.h>
#include <stdint.h>

#define MM 32768
#define DD 1152
#define HH 4608

// ---- scratch (__device__ globals; no allocation allowed) ----
__device__ float    g_sx[MM];
__device__ float    g_s2[MM];
__device__ unsigned g_amax[MM];
__device__ __half   g_aq1[(size_t)MM * DD];
__device__ __half   g_aq2[(size_t)MM * HH];
__device__ float    g_h  [(size_t)MM * HH];
__device__ __half   g_w1hi[(size_t)HH * DD], g_w1lo[(size_t)HH * DD];
__device__ __half   g_w2hi[(size_t)HH * DD];

__device__ __forceinline__ uint32_t swz(uint32_t b) {
    // 128B-row XOR swizzle: bits[6:4] ^= row%8 (row stride = 128B)
    return b ^ (((b >> 7) & 7u) << 4);
}
__device__ __forceinline__ uint32_t smem_u32(const void* p) {
    uint32_t a;
    asm("{ .reg .u64 t; cvta.to.shared.u64 t, %1; cvt.u32.u64 %0, t; }" : "=r"(a) : "l"(p));
    return a;
}
__device__ __forceinline__ void ldm4(uint32_t* r, uint32_t addr) {
    asm volatile("ldmatrix.sync.aligned.m8n8.x4.shared.b16 {%0,%1,%2,%3}, [%4];"
        : "=r"(r[0]), "=r"(r[1]), "=r"(r[2]), "=r"(r[3]) : "r"(addr));
}
__device__ __forceinline__ void mma16816(float* d, const uint32_t* a, uint32_t b0, uint32_t b1) {
    asm volatile("mma.sync.aligned.m16n8k16.row.col.f32.f16.f16.f32 "
        "{%0,%1,%2,%3}, {%4,%5,%6,%7}, {%8,%9}, {%0,%1,%2,%3};"
        : "+f"(d[0]), "+f"(d[1]), "+f"(d[2]), "+f"(d[3])
        : "r"(a[0]), "r"(a[1]), "r"(a[2]), "r"(a[3]), "r"(b0), "r"(b1));
}
// fp16-accumulate variant (used ONLY for the tiny lo-plane correction)
__device__ __forceinline__ void mma16816h(uint32_t* c, const uint32_t* a, uint32_t b0, uint32_t b1) {
    asm volatile("mma.sync.aligned.m16n8k16.row.col.f16.f16.f16.f16 "
        "{%0,%1}, {%2,%3,%4,%5}, {%6,%7}, {%0,%1};"
        : "+r"(c[0]), "+r"(c[1])
        : "r"(a[0]), "r"(a[1]), "r"(a[2]), "r"(a[3]), "r"(b0), "r"(b1));
}
__device__ __forceinline__ void cpa16(uint32_t dst, const void* src) {
    asm volatile("cp.async.cg.shared.global [%0], [%1], 16;" :: "r"(dst), "l"(src));
}
#define CP_COMMIT() asm volatile("cp.async.commit_group;" ::: "memory")
#define CP_WAIT1()  asm volatile("cp.async.wait_group 1;" ::: "memory")

__device__ __forceinline__ float gelu_exact(float v) {
    return 0.5f * v * (1.0f + erff(v * 0.70710678118654752f));
}

// ---------------------------------------------------------------------------
__global__ void pack_w1(const float* __restrict__ W, size_t total,
                        __half* __restrict__ hi, __half* __restrict__ lo) {
    for (size_t i = (size_t)blockIdx.x * blockDim.x + threadIdx.x; i < total;
         i += (size_t)gridDim.x * blockDim.x) {
        float w = W[i];
        __half h = __float2half_rn(w);
        hi[i] = h;
        lo[i] = __float2half_rn(w - __half2float(h));
    }
}
__global__ void pack_w2(const float* __restrict__ W, size_t total,
                        __half* __restrict__ hi) {
    for (size_t i = (size_t)blockIdx.x * blockDim.x + threadIdx.x; i < total;
         i += (size_t)gridDim.x * blockDim.x)
        hi[i] = __float2half_rn(W[i]);
}

__global__ void fq_input(const float* __restrict__ x, const int* __restrict__ ridx) {
    int m = blockIdx.x;
    const float* xr = x + (size_t)m * DD;
    __shared__ float red[4];
    float amax = 0.f;
    for (int d = threadIdx.x; d < DD; d += 128) amax = fmaxf(amax, fabsf(xr[ridx[d]]));
    #pragma unroll
    for (int o = 16; o; o >>= 1) amax = fmaxf(amax, __shfl_xor_sync(~0u, amax, o));
    if ((threadIdx.x & 31) == 0) red[threadIdx.x >> 5] = amax;
    __syncthreads();
    amax = fmaxf(fmaxf(red[0], red[1]), fmaxf(red[2], red[3]));
    float s = fmaxf(amax / 127.0f, 1e-8f);
    if (threadIdx.x == 0) g_sx[m] = s;
    __half* orow = g_aq1 + (size_t)m * DD;
    for (int p = threadIdx.x; p < DD / 2; p += 128) {
        float q0 = fminf(fmaxf(rintf(xr[ridx[2*p]]   / s), -128.f), 127.f);
        float q1 = fminf(fmaxf(rintf(xr[ridx[2*p+1]] / s), -128.f), 127.f);
        *(__half2*)(orow + 2*p) = __floats2half2_rn(q0, q1);
    }
}

__global__ void quantize_h() {
    int m = blockIdx.x;
    float s = fmaxf(__uint_as_float(g_amax[m]) / 127.0f, 1e-8f);
    if (threadIdx.x == 0) g_s2[m] = s;
    const float* hr = g_h + (size_t)m * HH;
    __half* orow = g_aq2 + (size_t)m * HH;
    for (int p = threadIdx.x; p < HH / 2; p += 256) {
        float2 v = *(const float2*)(hr + 2*p);
        float q0 = fminf(fmaxf(rintf(v.x / s), -128.f), 127.f);
        float q1 = fminf(fmaxf(rintf(v.y / s), -128.f), 127.f);
        *(__half2*)(orow + 2*p) = __floats2half2_rn(q0, q1);
    }
}

// ---------------------------------------------------------------------------
// GEMM1: hi-pass f32-acc + lo-pass f16-acc (lo term ~5e-4 of h; f16
// accumulation over full K adds ~2e-6 relative). CTA 128x128, BK=64,
// 2-stage cp.async, 2 CTAs/SM, 8 warps (4m x 2n), warp tile 32x64.
// ---------------------------------------------------------------------------
__global__ void __launch_bounds__(256, 2)
gemm1_mma(const __half* __restrict__ A, const __half* __restrict__ Bh,
          const __half* __restrict__ Bl, const float* __restrict__ bias,
          const float* __restrict__ rowscale, float* __restrict__ C,
          int ldc, int K, unsigned* __restrict__ amaxU)
{
    constexpr uint32_t STAGE = 49152u;   // A16K | Bh16K | Bl16K
    extern __shared__ char smem[];
    const uint32_t sb = smem_u32(smem);
    const int tid = threadIdx.x;
    const int wid = tid >> 5, lane = tid & 31;
    const int wm = wid & 3, wn = wid >> 2;     // 4 (m) x 2 (n)
    const int bm = blockIdx.y * 128, bn = blockIdx.x * 128;
    const int nk = K >> 6;

    // swz(b + g*2048) = swz(b) + g*2048 (row%8 preserved) -> single base each.
    const int lr = lane & 15, lc = lane >> 4;
    const uint32_t aoff0 = swz((uint32_t)((wm * 32 + lr) * 128 + lc * 16));
    const uint32_t boff0 = swz((uint32_t)((wn * 64 + lr) * 128 + lc * 16));

    float acc[2][8][4];
    uint32_t acc16[2][8][2];
    #pragma unroll
    for (int i = 0; i < 2; i++)
        #pragma unroll
        for (int j = 0; j < 8; j++) {
            #pragma unroll
            for (int l = 0; l < 4; l++) acc[i][j][l] = 0.f;
            acc16[i][j][0] = 0u; acc16[i][j][1] = 0u;
        }

    const uint32_t fd0 = swz((uint32_t)((tid >> 3) * 128 + (tid & 7) * 16));
    const size_t   fs0 = (size_t)(tid >> 3) * K + (tid & 7) * 8;
    const __half* fA  = A  + (size_t)bm * K + fs0;
    const __half* fBh = Bh + (size_t)bn * K + fs0;
    const __half* fBl = Bl + (size_t)bn * K + fs0;
    const size_t rstep = (size_t)32 * K;

    auto fill = [&](int s, int k0) {
        uint32_t st = sb + (uint32_t)s * STAGE + fd0;
        #pragma unroll
        for (int r = 0; r < 4; r++) {
            cpa16(st + r * 4096u,            fA  + r * rstep + k0);
            cpa16(st + 16384u + r * 4096u,   fBh + r * rstep + k0);
            cpa16(st + 32768u + r * 4096u,   fBl + r * rstep + k0);
        }
    };

    fill(0, 0);  CP_COMMIT();
    if (nk > 1) fill(1, 64);
    CP_COMMIT();

    for (int ks = 0; ks < nk; ks++) {
        CP_WAIT1();
        __syncthreads();
        const uint32_t st = sb + (uint32_t)(ks & 1) * STAGE;

        #pragma unroll
        for (int kk = 0; kk < 4; kk++) {
            const uint32_t kx = (uint32_t)(kk * 32);
            const uint32_t ab = st + (aoff0 ^ kx);
            const uint32_t bbse = st + (boff0 ^ kx);
            uint32_t a[2][4], b[2][4];
            ldm4(a[0], ab);
            ldm4(a[1], ab + 2048u);          // mt=1: +16 rows = +2048 bytes
            // ---- hi plane: f32 accumulate ----
            ldm4(b[0], bbse + 16384u);
            ldm4(b[1], bbse + 16384u + 2048u);
            #pragma unroll
            for (int mt = 0; mt < 2; mt++) {
                mma16816(acc[mt][0], a[mt], b[0][0], b[0][2]);
                mma16816(acc[mt][1], a[mt], b[0][1], b[0][3]);
                mma16816(acc[mt][2], a[mt], b[1][0], b[1][2]);
                mma16816(acc[mt][3], a[mt], b[1][1], b[1][3]);
            }
            ldm4(b[0], bbse + 16384u + 4096u);
            ldm4(b[1], bbse + 16384u + 6144u);
            #pragma unroll
            for (int mt = 0; mt < 2; mt++) {
                mma16816(acc[mt][4], a[mt], b[0][0], b[0][2]);
                mma16816(acc[mt][5], a[mt], b[0][1], b[0][3]);
                mma16816(acc[mt][6], a[mt], b[1][0], b[1][2]);
                mma16816(acc[mt][7], a[mt], b[1][1], b[1][3]);
            }
            // ---- lo plane: f16 accumulate ----
            ldm4(b[0], bbse + 32768u);
            ldm4(b[1], bbse + 32768u + 2048u);
            #pragma unroll
            for (int mt = 0; mt < 2; mt++) {
                mma16816h(acc16[mt][0], a[mt], b[0][0], b[0][2]);
                mma16816h(acc16[mt][1], a[mt], b[0][1], b[0][3]);
                mma16816h(acc16[mt][2], a[mt], b[1][0], b[1][2]);
                mma16816h(acc16[mt][3], a[mt], b[1][1], b[1][3]);
            }
            ldm4(b[0], bbse + 32768u + 4096u);
            ldm4(b[1], bbse + 32768u + 6144u);
            #pragma unroll
            for (int mt = 0; mt < 2; mt++) {
                mma16816h(acc16[mt][4], a[mt], b[0][0], b[0][2]);
                mma16816h(acc16[mt][5], a[mt], b[0][1], b[0][3]);
                mma16816h(acc16[mt][6], a[mt], b[1][0], b[1][2]);
                mma16816h(acc16[mt][7], a[mt], b[1][1], b[1][3]);
            }
        }

        __syncthreads();
        if (ks + 2 < nk) fill(ks & 1, (ks + 2) * 64);
        CP_COMMIT();
    }

    // ---- epilogue: combine hi+lo, bias + GELU + store + row absmax ----
    const int q = lane >> 2, c2 = (lane & 3) * 2;
    #pragma unroll
    for (int mt = 0; mt < 2; mt++) {
        int r0 = bm + wm * 32 + mt * 16 + q;
        float rs0 = rowscale[r0], rs1 = rowscale[r0 + 8];
        float mx0 = 0.f, mx1 = 0.f;
        #pragma unroll
        for (int nt = 0; nt < 8; nt++) {
            int col = bn + wn * 64 + nt * 8 + c2;
            float2 bb = *(const float2*)(bias + col);
            float2 l0 = __half22float2(*(__half2*)&acc16[mt][nt][0]);
            float2 l1 = __half22float2(*(__half2*)&acc16[mt][nt][1]);
            float v0 = gelu_exact((acc[mt][nt][0] + l0.x) * rs0 + bb.x);
            float v1 = gelu_exact((acc[mt][nt][1] + l0.y) * rs0 + bb.y);
            float v2 = gelu_exact((acc[mt][nt][2] + l1.x) * rs1 + bb.x);
            float v3 = gelu_exact((acc[mt][nt][3] + l1.y) * rs1 + bb.y);
            mx0 = fmaxf(mx0, fmaxf(fabsf(v0), fabsf(v1)));
            mx1 = fmaxf(mx1, fmaxf(fabsf(v2), fabsf(v3)));
            float2 o0 = {v0, v1}, o1 = {v2, v3};
            *(float2*)(C + (size_t)r0 * ldc + col) = o0;
            *(float2*)(C + (size_t)(r0 + 8) * ldc + col) = o1;
        }
        mx0 = fmaxf(mx0, __shfl_xor_sync(~0u, mx0, 1));
        mx0 = fmaxf(mx0, __shfl_xor_sync(~0u, mx0, 2));
        mx1 = fmaxf(mx1, __shfl_xor_sync(~0u, mx1, 1));
        mx1 = fmaxf(mx1, __shfl_xor_sync(~0u, mx1, 2));
        if ((lane & 3) == 0) {
            atomicMax(amaxU + r0,     __float_as_uint(mx0));
            atomicMax(amaxU + r0 + 8, __float_as_uint(mx1));
        }
    }
}

// ---------------------------------------------------------------------------
// GEMM2 (hi only): CTA 128x128, BK=64, 3-stage ring, single barrier/k-step,
// 8 warps (4m x 2n), warp tile 32x64, 2 CTAs/SM. (R11 engine, measured-best.)
// ---------------------------------------------------------------------------
__global__ void __launch_bounds__(256, 2)
gemm2_mma(const __half* __restrict__ A, const __half* __restrict__ Bh,
          const float* __restrict__ bias, const float* __restrict__ rowscale,
          float* __restrict__ C, int ldc, int K)
{
    constexpr uint32_t STAGE = 32768u;   // A16K | Bh16K
    extern __shared__ char smem[];
    const uint32_t sb = smem_u32(smem);
    const int tid = threadIdx.x;
    const int wid = tid >> 5, lane = tid & 31;
    const int wm = wid & 3, wn = wid >> 2;
    const int bm = blockIdx.y * 128, bn = blockIdx.x * 128;
    const int nk = K >> 6;

    const int lr = lane & 15, lc = lane >> 4;
    uint32_t aoff[2], boff[4];
    #pragma unroll
    for (int mt = 0; mt < 2; mt++)
        aoff[mt] = swz((uint32_t)((wm * 32 + mt * 16 + lr) * 128 + lc * 16));
    #pragma unroll
    for (int g = 0; g < 4; g++)
        boff[g] = 16384u + swz((uint32_t)((wn * 64 + g * 16 + lr) * 128 + lc * 16));

    float acc[2][8][4];
    #pragma unroll
    for (int i = 0; i < 2; i++)
        #pragma unroll
        for (int j = 0; j < 8; j++)
            #pragma unroll
            for (int l = 0; l < 4; l++) acc[i][j][l] = 0.f;

    const uint32_t fd0 = swz((uint32_t)((tid >> 3) * 128 + (tid & 7) * 16));
    const size_t   fs0 = (size_t)(tid >> 3) * K + (tid & 7) * 8;
    const __half* fA  = A  + (size_t)bm * K + fs0;
    const __half* fBh = Bh + (size_t)bn * K + fs0;
    const size_t rstep = (size_t)32 * K;

    auto fill = [&](int s, int k0) {
        uint32_t st = sb + (uint32_t)s * STAGE + fd0;
        #pragma unroll
        for (int r = 0; r < 4; r++) {
            cpa16(st + r * 4096u,          fA  + r * rstep + k0);
            cpa16(st + 16384u + r * 4096u, fBh + r * rstep + k0);
        }
    };

    fill(0, 0);  CP_COMMIT();
    fill(1, 64); CP_COMMIT();

    int stage = 0;
    for (int ks = 0; ks < nk; ks++) {
        CP_WAIT1();
        __syncthreads();
        if (ks + 2 < nk) {
            int ts = stage + 2; if (ts >= 3) ts -= 3;
            fill(ts, (ks + 2) * 64);
        }
        CP_COMMIT();

        const uint32_t st = sb + (uint32_t)stage * STAGE;
        #pragma unroll
        for (int kk = 0; kk < 4; kk++) {
            const uint32_t kx = (uint32_t)(kk * 32);
            uint32_t a[2][4], b[4][4];
            #pragma unroll
            for (int mt = 0; mt < 2; mt++) ldm4(a[mt], st + (aoff[mt] ^ kx));
            #pragma unroll
            for (int g = 0; g < 4; g++) ldm4(b[g], st + (boff[g] ^ kx));
            #pragma unroll
            for (int mt = 0; mt < 2; mt++)
                #pragma unroll
                for (int g = 0; g < 4; g++) {
                    mma16816(acc[mt][2*g],   a[mt], b[g][0], b[g][2]);
                    mma16816(acc[mt][2*g+1], a[mt], b[g][1], b[g][3]);
                }
        }
        if (++stage == 3) stage = 0;
    }

    const int q = lane >> 2, c2 = (lane & 3) * 2;
    #pragma unroll
    for (int mt = 0; mt < 2; mt++) {
        int r0 = bm + wm * 32 + mt * 16 + q;
        float rs0 = rowscale[r0], rs1 = rowscale[r0 + 8];
        #pragma unroll
        for (int nt = 0; nt < 8; nt++) {
            int col = bn + wn * 64 + nt * 8 + c2;
            float2 bb = *(const float2*)(bias + col);
            float2 o0 = {acc[mt][nt][0] * rs0 + bb.x, acc[mt][nt][1] * rs0 + bb.y};
            float2 o1 = {acc[mt][nt][2] * rs1 + bb.x, acc[mt][nt][3] * rs1 + bb.y};
            *(float2*)(C + (size_t)r0 * ldc + col) = o0;
            *(float2*)(C + (size_t)(r0 + 8) * ldc + col) = o1;
        }
    }
}

// ---------------------------------------------------------------------------
extern "C" void kernel_launch(void* const* d_in, const int* in_sizes, int n_in,
                              void* d_out, int out_size) {
    const float* x   = (const float*)d_in[0];
    const int*   idx = (const int*)d_in[1];
    const float* W1  = (const float*)d_in[2];
    const float* b1  = (const float*)d_in[3];
    const float* W2  = (const float*)d_in[4];
    const float* b2  = (const float*)d_in[5];
    float* out = (float*)d_out;

    void *aq1, *aq2, *hptr, *w1h, *w1l, *w2h, *sx, *s2, *am;
    cudaGetSymbolAddress(&aq1, g_aq1);  cudaGetSymbolAddress(&aq2, g_aq2);
    cudaGetSymbolAddress(&hptr, g_h);
    cudaGetSymbolAddress(&w1h, g_w1hi); cudaGetSymbolAddress(&w1l, g_w1lo);
    cudaGetSymbolAddress(&w2h, g_w2hi);
    cudaGetSymbolAddress(&sx, g_sx);    cudaGetSymbolAddress(&s2, g_s2);
    cudaGetSymbolAddress(&am, g_amax);

    const int SMEM1 = 2 * 49152;   // 96KB -> 2 CTAs/SM
    const int SMEM2 = 3 * 32768;   // 96KB -> 2 CTAs/SM
    cudaFuncSetAttribute((const void*)gemm1_mma, cudaFuncAttributeMaxDynamicSharedMemorySize, SMEM1);
    cudaFuncSetAttribute((const void*)gemm2_mma, cudaFuncAttributeMaxDynamicSharedMemorySize, SMEM2);

    pack_w1<<<2048, 256>>>(W1, (size_t)HH * DD, (__half*)w1h, (__half*)w1l);
    pack_w2<<<2048, 256>>>(W2, (size_t)DD * HH, (__half*)w2h);
    cudaMemsetAsync(am, 0, MM * sizeof(unsigned));
    fq_input<<<MM, 128>>>(x, idx);

    gemm1_mma<<<dim3(HH / 128, MM / 128), 256, SMEM1>>>(
        (const __half*)aq1, (const __half*)w1h, (const __half*)w1l,
        b1, (const float*)sx, (float*)hptr, HH, DD, (unsigned*)am);

    quantize_h<<<MM, 256>>>();

    gemm2_mma<<<dim3(DD / 128, MM / 128), 256, SMEM2>>>(
        (const __half*)aq2, (const __half*)w2h,
        b2, (const float*)s2, out, DD, HH);
}

// round 16
// speedup vs baseline: 1.1057x; 1.0215x over previous
#include <cuda_runtime.h>
#include <cuda_fp16.h>
#include <math.h>
#include <stdint.h>

#define MM 32768
#define DD 1152
#define HH 4608

// ---- scratch (__device__ globals; no allocation allowed) ----
__device__ float    g_sx[MM];
__device__ float    g_s2[MM];
__device__ unsigned g_amax[MM];
__device__ __half   g_aq1[(size_t)MM * DD];
__device__ __half   g_aq2[(size_t)MM * HH];
__device__ float    g_h  [(size_t)MM * HH];
__device__ __half   g_w1hi[(size_t)HH * DD], g_w1lo[(size_t)HH * DD];
__device__ __half   g_w2hi[(size_t)HH * DD];

__device__ __forceinline__ uint32_t swz(uint32_t b) {
    // 128B-row XOR swizzle: bits[6:4] ^= row%8 (row stride = 128B)
    return b ^ (((b >> 7) & 7u) << 4);
}
__device__ __forceinline__ uint32_t smem_u32(const void* p) {
    uint32_t a;
    asm("{ .reg .u64 t; cvta.to.shared.u64 t, %1; cvt.u32.u64 %0, t; }" : "=r"(a) : "l"(p));
    return a;
}
__device__ __forceinline__ void ldm4(uint32_t* r, uint32_t addr) {
    asm volatile("ldmatrix.sync.aligned.m8n8.x4.shared.b16 {%0,%1,%2,%3}, [%4];"
        : "=r"(r[0]), "=r"(r[1]), "=r"(r[2]), "=r"(r[3]) : "r"(addr));
}
__device__ __forceinline__ void mma16816(float* d, const uint32_t* a, uint32_t b0, uint32_t b1) {
    asm volatile("mma.sync.aligned.m16n8k16.row.col.f32.f16.f16.f32 "
        "{%0,%1,%2,%3}, {%4,%5,%6,%7}, {%8,%9}, {%0,%1,%2,%3};"
        : "+f"(d[0]), "+f"(d[1]), "+f"(d[2]), "+f"(d[3])
        : "r"(a[0]), "r"(a[1]), "r"(a[2]), "r"(a[3]), "r"(b0), "r"(b1));
}
// fp16-accumulate variant (used ONLY for the tiny lo-plane correction)
__device__ __forceinline__ void mma16816h(uint32_t* c, const uint32_t* a, uint32_t b0, uint32_t b1) {
    asm volatile("mma.sync.aligned.m16n8k16.row.col.f16.f16.f16.f16 "
        "{%0,%1}, {%2,%3,%4,%5}, {%6,%7}, {%0,%1};"
        : "+r"(c[0]), "+r"(c[1])
        : "r"(a[0]), "r"(a[1]), "r"(a[2]), "r"(a[3]), "r"(b0), "r"(b1));
}
__device__ __forceinline__ void cpa16(uint32_t dst, const void* src) {
    asm volatile("cp.async.cg.shared.global [%0], [%1], 16;" :: "r"(dst), "l"(src));
}
#define CP_COMMIT() asm volatile("cp.async.commit_group;" ::: "memory")
#define CP_WAIT1()  asm volatile("cp.async.wait_group 1;" ::: "memory")

__device__ __forceinline__ float gelu_exact(float v) {
    return 0.5f * v * (1.0f + erff(v * 0.70710678118654752f));
}

// ---------------------------------------------------------------------------
__global__ void pack_w1(const float* __restrict__ W, size_t total,
                        __half* __restrict__ hi, __half* __restrict__ lo) {
    for (size_t i = (size_t)blockIdx.x * blockDim.x + threadIdx.x; i < total;
         i += (size_t)gridDim.x * blockDim.x) {
        float w = W[i];
        __half h = __float2half_rn(w);
        hi[i] = h;
        lo[i] = __float2half_rn(w - __half2float(h));
    }
}
__global__ void pack_w2(const float* __restrict__ W, size_t total,
                        __half* __restrict__ hi) {
    for (size_t i = (size_t)blockIdx.x * blockDim.x + threadIdx.x; i < total;
         i += (size_t)gridDim.x * blockDim.x)
        hi[i] = __float2half_rn(W[i]);
}

__global__ void fq_input(const float* __restrict__ x, const int* __restrict__ ridx) {
    int m = blockIdx.x;
    const float* xr = x + (size_t)m * DD;
    __shared__ float red[4];
    float amax = 0.f;
    for (int d = threadIdx.x; d < DD; d += 128) amax = fmaxf(amax, fabsf(xr[ridx[d]]));
    #pragma unroll
    for (int o = 16; o; o >>= 1) amax = fmaxf(amax, __shfl_xor_sync(~0u, amax, o));
    if ((threadIdx.x & 31) == 0) red[threadIdx.x >> 5] = amax;
    __syncthreads();
    amax = fmaxf(fmaxf(red[0], red[1]), fmaxf(red[2], red[3]));
    float s = fmaxf(amax / 127.0f, 1e-8f);
    if (threadIdx.x == 0) g_sx[m] = s;
    __half* orow = g_aq1 + (size_t)m * DD;
    for (int p = threadIdx.x; p < DD / 2; p += 128) {
        float q0 = fminf(fmaxf(rintf(xr[ridx[2*p]]   / s), -128.f), 127.f);
        float q1 = fminf(fmaxf(rintf(xr[ridx[2*p+1]] / s), -128.f), 127.f);
        *(__half2*)(orow + 2*p) = __floats2half2_rn(q0, q1);
    }
}

__global__ void quantize_h() {
    int m = blockIdx.x;
    float s = fmaxf(__uint_as_float(g_amax[m]) / 127.0f, 1e-8f);
    if (threadIdx.x == 0) g_s2[m] = s;
    const float* hr = g_h + (size_t)m * HH;
    __half* orow = g_aq2 + (size_t)m * HH;
    for (int p = threadIdx.x; p < HH / 4; p += 256) {
        float4 v = *(const float4*)(hr + 4*p);
        float q0 = fminf(fmaxf(rintf(v.x / s), -128.f), 127.f);
        float q1 = fminf(fmaxf(rintf(v.y / s), -128.f), 127.f);
        float q2 = fminf(fmaxf(rintf(v.z / s), -128.f), 127.f);
        float q3 = fminf(fmaxf(rintf(v.w / s), -128.f), 127.f);
        *(__half2*)(orow + 4*p)     = __floats2half2_rn(q0, q1);
        *(__half2*)(orow + 4*p + 2) = __floats2half2_rn(q2, q3);
    }
}

// ---------------------------------------------------------------------------
// GEMM1: hi-pass f32-acc + lo-pass f16-acc. CTA 128x128, BK=64, 2-stage
// cp.async, 2 CTAs/SM, 8 warps (4m x 2n), warp tile 32x64.
// Warp-rotated kk order ((kk+wid)&3) decorrelates post-barrier LDSM bursts.
// ---------------------------------------------------------------------------
__global__ void __launch_bounds__(256, 2)
gemm1_mma(const __half* __restrict__ A, const __half* __restrict__ Bh,
          const __half* __restrict__ Bl, const float* __restrict__ bias,
          const float* __restrict__ rowscale, float* __restrict__ C,
          int ldc, int K, unsigned* __restrict__ amaxU)
{
    constexpr uint32_t STAGE = 49152u;   // A16K | Bh16K | Bl16K
    extern __shared__ char smem[];
    const uint32_t sb = smem_u32(smem);
    const int tid = threadIdx.x;
    const int wid = tid >> 5, lane = tid & 31;
    const int wm = wid & 3, wn = wid >> 2;     // 4 (m) x 2 (n)
    const int bm = blockIdx.y * 128, bn = blockIdx.x * 128;
    const int nk = K >> 6;

    const int lr = lane & 15, lc = lane >> 4;
    const uint32_t aoff0 = swz((uint32_t)((wm * 32 + lr) * 128 + lc * 16));
    const uint32_t boff0 = swz((uint32_t)((wn * 64 + lr) * 128 + lc * 16));

    float acc[2][8][4];
    uint32_t acc16[2][8][2];
    #pragma unroll
    for (int i = 0; i < 2; i++)
        #pragma unroll
        for (int j = 0; j < 8; j++) {
            #pragma unroll
            for (int l = 0; l < 4; l++) acc[i][j][l] = 0.f;
            acc16[i][j][0] = 0u; acc16[i][j][1] = 0u;
        }

    const uint32_t fd0 = swz((uint32_t)((tid >> 3) * 128 + (tid & 7) * 16));
    const size_t   fs0 = (size_t)(tid >> 3) * K + (tid & 7) * 8;
    const __half* fA  = A  + (size_t)bm * K + fs0;
    const __half* fBh = Bh + (size_t)bn * K + fs0;
    const __half* fBl = Bl + (size_t)bn * K + fs0;
    const size_t rstep = (size_t)32 * K;

    auto fill = [&](int s, int k0) {
        uint32_t st = sb + (uint32_t)s * STAGE + fd0;
        #pragma unroll
        for (int r = 0; r < 4; r++) {
            cpa16(st + r * 4096u,            fA  + r * rstep + k0);
            cpa16(st + 16384u + r * 4096u,   fBh + r * rstep + k0);
            cpa16(st + 32768u + r * 4096u,   fBl + r * rstep + k0);
        }
    };

    fill(0, 0);  CP_COMMIT();
    if (nk > 1) fill(1, 64);
    CP_COMMIT();

    for (int ks = 0; ks < nk; ks++) {
        CP_WAIT1();
        __syncthreads();
        const uint32_t st = sb + (uint32_t)(ks & 1) * STAGE;

        #pragma unroll
        for (int kk = 0; kk < 4; kk++) {
            // per-warp rotation of the kk schedule (order-invariant sum over k)
            const uint32_t kx = (uint32_t)(((kk + wid) & 3) * 32);
            const uint32_t ab = st + (aoff0 ^ kx);
            const uint32_t bbse = st + (boff0 ^ kx);
            uint32_t a[2][4], b[2][4];
            ldm4(a[0], ab);
            ldm4(a[1], ab + 2048u);
            // ---- hi plane: f32 accumulate ----
            ldm4(b[0], bbse + 16384u);
            ldm4(b[1], bbse + 16384u + 2048u);
            #pragma unroll
            for (int mt = 0; mt < 2; mt++) {
                mma16816(acc[mt][0], a[mt], b[0][0], b[0][2]);
                mma16816(acc[mt][1], a[mt], b[0][1], b[0][3]);
                mma16816(acc[mt][2], a[mt], b[1][0], b[1][2]);
                mma16816(acc[mt][3], a[mt], b[1][1], b[1][3]);
            }
            ldm4(b[0], bbse + 16384u + 4096u);
            ldm4(b[1], bbse + 16384u + 6144u);
            #pragma unroll
            for (int mt = 0; mt < 2; mt++) {
                mma16816(acc[mt][4], a[mt], b[0][0], b[0][2]);
                mma16816(acc[mt][5], a[mt], b[0][1], b[0][3]);
                mma16816(acc[mt][6], a[mt], b[1][0], b[1][2]);
                mma16816(acc[mt][7], a[mt], b[1][1], b[1][3]);
            }
            // ---- lo plane: f16 accumulate ----
            ldm4(b[0], bbse + 32768u);
            ldm4(b[1], bbse + 32768u + 2048u);
            #pragma unroll
            for (int mt = 0; mt < 2; mt++) {
                mma16816h(acc16[mt][0], a[mt], b[0][0], b[0][2]);
                mma16816h(acc16[mt][1], a[mt], b[0][1], b[0][3]);
                mma16816h(acc16[mt][2], a[mt], b[1][0], b[1][2]);
                mma16816h(acc16[mt][3], a[mt], b[1][1], b[1][3]);
            }
            ldm4(b[0], bbse + 32768u + 4096u);
            ldm4(b[1], bbse + 32768u + 6144u);
            #pragma unroll
            for (int mt = 0; mt < 2; mt++) {
                mma16816h(acc16[mt][4], a[mt], b[0][0], b[0][2]);
                mma16816h(acc16[mt][5], a[mt], b[0][1], b[0][3]);
                mma16816h(acc16[mt][6], a[mt], b[1][0], b[1][2]);
                mma16816h(acc16[mt][7], a[mt], b[1][1], b[1][3]);
            }
        }

        __syncthreads();
        if (ks + 2 < nk) fill(ks & 1, (ks + 2) * 64);
        CP_COMMIT();
    }

    // ---- epilogue: combine hi+lo, bias + GELU + store + row absmax ----
    const int q = lane >> 2, c2 = (lane & 3) * 2;
    #pragma unroll
    for (int mt = 0; mt < 2; mt++) {
        int r0 = bm + wm * 32 + mt * 16 + q;
        float rs0 = rowscale[r0], rs1 = rowscale[r0 + 8];
        float mx0 = 0.f, mx1 = 0.f;
        #pragma unroll
        for (int nt = 0; nt < 8; nt++) {
            int col = bn + wn * 64 + nt * 8 + c2;
            float2 bb = *(const float2*)(bias + col);
            float2 l0 = __half22float2(*(__half2*)&acc16[mt][nt][0]);
            float2 l1 = __half22float2(*(__half2*)&acc16[mt][nt][1]);
            float v0 = gelu_exact((acc[mt][nt][0] + l0.x) * rs0 + bb.x);
            float v1 = gelu_exact((acc[mt][nt][1] + l0.y) * rs0 + bb.y);
            float v2 = gelu_exact((acc[mt][nt][2] + l1.x) * rs1 + bb.x);
            float v3 = gelu_exact((acc[mt][nt][3] + l1.y) * rs1 + bb.y);
            mx0 = fmaxf(mx0, fmaxf(fabsf(v0), fabsf(v1)));
            mx1 = fmaxf(mx1, fmaxf(fabsf(v2), fabsf(v3)));
            float2 o0 = {v0, v1}, o1 = {v2, v3};
            *(float2*)(C + (size_t)r0 * ldc + col) = o0;
            *(float2*)(C + (size_t)(r0 + 8) * ldc + col) = o1;
        }
        mx0 = fmaxf(mx0, __shfl_xor_sync(~0u, mx0, 1));
        mx0 = fmaxf(mx0, __shfl_xor_sync(~0u, mx0, 2));
        mx1 = fmaxf(mx1, __shfl_xor_sync(~0u, mx1, 1));
        mx1 = fmaxf(mx1, __shfl_xor_sync(~0u, mx1, 2));
        if ((lane & 3) == 0) {
            atomicMax(amaxU + r0,     __float_as_uint(mx0));
            atomicMax(amaxU + r0 + 8, __float_as_uint(mx1));
        }
    }
}

// ---------------------------------------------------------------------------
// GEMM2 (hi only): CTA 128x128, BK=64, 3-stage ring, single barrier/k-step,
// 8 warps (4m x 2n), warp tile 32x64, 2 CTAs/SM. Warp-rotated kk order.
// ---------------------------------------------------------------------------
__global__ void __launch_bounds__(256, 2)
gemm2_mma(const __half* __restrict__ A, const __half* __restrict__ Bh,
          const float* __restrict__ bias, const float* __restrict__ rowscale,
          float* __restrict__ C, int ldc, int K)
{
    constexpr uint32_t STAGE = 32768u;   // A16K | Bh16K
    extern __shared__ char smem[];
    const uint32_t sb = smem_u32(smem);
    const int tid = threadIdx.x;
    const int wid = tid >> 5, lane = tid & 31;
    const int wm = wid & 3, wn = wid >> 2;
    const int bm = blockIdx.y * 128, bn = blockIdx.x * 128;
    const int nk = K >> 6;

    const int lr = lane & 15, lc = lane >> 4;
    uint32_t aoff[2], boff[4];
    #pragma unroll
    for (int mt = 0; mt < 2; mt++)
        aoff[mt] = swz((uint32_t)((wm * 32 + mt * 16 + lr) * 128 + lc * 16));
    #pragma unroll
    for (int g = 0; g < 4; g++)
        boff[g] = 16384u + swz((uint32_t)((wn * 64 + g * 16 + lr) * 128 + lc * 16));

    float acc[2][8][4];
    #pragma unroll
    for (int i = 0; i < 2; i++)
        #pragma unroll
        for (int j = 0; j < 8; j++)
            #pragma unroll
            for (int l = 0; l < 4; l++) acc[i][j][l] = 0.f;

    const uint32_t fd0 = swz((uint32_t)((tid >> 3) * 128 + (tid & 7) * 16));
    const size_t   fs0 = (size_t)(tid >> 3) * K + (tid & 7) * 8;
    const __half* fA  = A  + (size_t)bm * K + fs0;
    const __half* fBh = Bh + (size_t)bn * K + fs0;
    const size_t rstep = (size_t)32 * K;

    auto fill = [&](int s, int k0) {
        uint32_t st = sb + (uint32_t)s * STAGE + fd0;
        #pragma unroll
        for (int r = 0; r < 4; r++) {
            cpa16(st + r * 4096u,          fA  + r * rstep + k0);
            cpa16(st + 16384u + r * 4096u, fBh + r * rstep + k0);
        }
    };

    fill(0, 0);  CP_COMMIT();
    fill(1, 64); CP_COMMIT();

    int stage = 0;
    for (int ks = 0; ks < nk; ks++) {
        CP_WAIT1();
        __syncthreads();
        if (ks + 2 < nk) {
            int ts = stage + 2; if (ts >= 3) ts -= 3;
            fill(ts, (ks + 2) * 64);
        }
        CP_COMMIT();

        const uint32_t st = sb + (uint32_t)stage * STAGE;
        #pragma unroll
        for (int kk = 0; kk < 4; kk++) {
            const uint32_t kx = (uint32_t)(((kk + wid) & 3) * 32);
            uint32_t a[2][4], b[4][4];
            #pragma unroll
            for (int mt = 0; mt < 2; mt++) ldm4(a[mt], st + (aoff[mt] ^ kx));
            #pragma unroll
            for (int g = 0; g < 4; g++) ldm4(b[g], st + (boff[g] ^ kx));
            #pragma unroll
            for (int mt = 0; mt < 2; mt++)
                #pragma unroll
                for (int g = 0; g < 4; g++) {
                    mma16816(acc[mt][2*g],   a[mt], b[g][0], b[g][2]);
                    mma16816(acc[mt][2*g+1], a[mt], b[g][1], b[g][3]);
                }
        }
        if (++stage == 3) stage = 0;
    }

    const int q = lane >> 2, c2 = (lane & 3) * 2;
    #pragma unroll
    for (int mt = 0; mt < 2; mt++) {
        int r0 = bm + wm * 32 + mt * 16 + q;
        float rs0 = rowscale[r0], rs1 = rowscale[r0 + 8];
        #pragma unroll
        for (int nt = 0; nt < 8; nt++) {
            int col = bn + wn * 64 + nt * 8 + c2;
            float2 bb = *(const float2*)(bias + col);
            float2 o0 = {acc[mt][nt][0] * rs0 + bb.x, acc[mt][nt][1] * rs0 + bb.y};
            float2 o1 = {acc[mt][nt][2] * rs1 + bb.x, acc[mt][nt][3] * rs1 + bb.y};
            *(float2*)(C + (size_t)r0 * ldc + col) = o0;
            *(float2*)(C + (size_t)(r0 + 8) * ldc + col) = o1;
        }
    }
}

// ---------------------------------------------------------------------------
extern "C" void kernel_launch(void* const* d_in, const int* in_sizes, int n_in,
                              void* d_out, int out_size) {
    const float* x   = (const float*)d_in[0];
    const int*   idx = (const int*)d_in[1];
    const float* W1  = (const float*)d_in[2];
    const float* b1  = (const float*)d_in[3];
    const float* W2  = (const float*)d_in[4];
    const float* b2  = (const float*)d_in[5];
    float* out = (float*)d_out;

    void *aq1, *aq2, *hptr, *w1h, *w1l, *w2h, *sx, *s2, *am;
    cudaGetSymbolAddress(&aq1, g_aq1);  cudaGetSymbolAddress(&aq2, g_aq2);
    cudaGetSymbolAddress(&hptr, g_h);
    cudaGetSymbolAddress(&w1h, g_w1hi); cudaGetSymbolAddress(&w1l, g_w1lo);
    cudaGetSymbolAddress(&w2h, g_w2hi);
    cudaGetSymbolAddress(&sx, g_sx);    cudaGetSymbolAddress(&s2, g_s2);
    cudaGetSymbolAddress(&am, g_amax);

    const int SMEM1 = 2 * 49152;   // 96KB -> 2 CTAs/SM
    const int SMEM2 = 3 * 32768;   // 96KB -> 2 CTAs/SM
    cudaFuncSetAttribute((const void*)gemm1_mma, cudaFuncAttributeMaxDynamicSharedMemorySize, SMEM1);
    cudaFuncSetAttribute((const void*)gemm2_mma, cudaFuncAttributeMaxDynamicSharedMemorySize, SMEM2);

    pack_w1<<<2048, 256>>>(W1, (size_t)HH * DD, (__half*)w1h, (__half*)w1l);
    pack_w2<<<2048, 256>>>(W2, (size_t)DD * HH, (__half*)w2h);
    cudaMemsetAsync(am, 0, MM * sizeof(unsigned));
    fq_input<<<MM, 128>>>(x, idx);

    gemm1_mma<<<dim3(HH / 128, MM / 128), 256, SMEM1>>>(
        (const __half*)aq1, (const __half*)w1h, (const __half*)w1l,
        b1, (const float*)sx, (float*)hptr, HH, DD, (unsigned*)am);

    quantize_h<<<MM, 256>>>();

    gemm2_mma<<<dim3(DD / 128, MM / 128), 256, SMEM2>>>(
        (const __half*)aq2, (const __half*)w2h,
        b2, (const float*)s2, out, DD, HH);
}

// round 17
// speedup vs baseline: 1.1235x; 1.0161x over previous
#include <cuda_runtime.h>
#include <cuda_fp16.h>
#include <math.h>
#include <stdint.h>

#define MM 32768
#define DD 1152
#define HH 4608

// ---- scratch (__device__ globals; no allocation allowed) ----
__device__ float    g_sx[MM];
__device__ float    g_s2[MM];
__device__ unsigned g_amax[MM];
__device__ __half   g_aq1[(size_t)MM * DD];
__device__ __half   g_aq2[(size_t)MM * HH];
__device__ float    g_h  [(size_t)MM * HH];
__device__ __half   g_w1hi[(size_t)HH * DD], g_w1lo[(size_t)HH * DD];
__device__ __half   g_w2hi[(size_t)HH * DD];

__device__ __forceinline__ uint32_t swz(uint32_t b) {
    // 128B-row XOR swizzle: bits[6:4] ^= row%8 (row stride = 128B)
    return b ^ (((b >> 7) & 7u) << 4);
}
__device__ __forceinline__ uint32_t smem_u32(const void* p) {
    uint32_t a;
    asm("{ .reg .u64 t; cvta.to.shared.u64 t, %1; cvt.u32.u64 %0, t; }" : "=r"(a) : "l"(p));
    return a;
}
__device__ __forceinline__ void ldm4(uint32_t* r, uint32_t addr) {
    asm volatile("ldmatrix.sync.aligned.m8n8.x4.shared.b16 {%0,%1,%2,%3}, [%4];"
        : "=r"(r[0]), "=r"(r[1]), "=r"(r[2]), "=r"(r[3]) : "r"(addr));
}
__device__ __forceinline__ void mma16816(float* d, const uint32_t* a, uint32_t b0, uint32_t b1) {
    asm volatile("mma.sync.aligned.m16n8k16.row.col.f32.f16.f16.f32 "
        "{%0,%1,%2,%3}, {%4,%5,%6,%7}, {%8,%9}, {%0,%1,%2,%3};"
        : "+f"(d[0]), "+f"(d[1]), "+f"(d[2]), "+f"(d[3])
        : "r"(a[0]), "r"(a[1]), "r"(a[2]), "r"(a[3]), "r"(b0), "r"(b1));
}
// fp16-accumulate variant (used ONLY for the tiny lo-plane correction)
__device__ __forceinline__ void mma16816h(uint32_t* c, const uint32_t* a, uint32_t b0, uint32_t b1) {
    asm volatile("mma.sync.aligned.m16n8k16.row.col.f16.f16.f16.f16 "
        "{%0,%1}, {%2,%3,%4,%5}, {%6,%7}, {%0,%1};"
        : "+r"(c[0]), "+r"(c[1])
        : "r"(a[0]), "r"(a[1]), "r"(a[2]), "r"(a[3]), "r"(b0), "r"(b1));
}
__device__ __forceinline__ void cpa16(uint32_t dst, const void* src) {
    asm volatile("cp.async.cg.shared.global [%0], [%1], 16;" :: "r"(dst), "l"(src));
}
#define CP_COMMIT() asm volatile("cp.async.commit_group;" ::: "memory")
#define CP_WAIT1()  asm volatile("cp.async.wait_group 1;" ::: "memory")

__device__ __forceinline__ float gelu_exact(float v) {
    return 0.5f * v * (1.0f + erff(v * 0.70710678118654752f));
}

// ---------------------------------------------------------------------------
__global__ void pack_w1(const float* __restrict__ W, size_t total,
                        __half* __restrict__ hi, __half* __restrict__ lo) {
    for (size_t i = (size_t)blockIdx.x * blockDim.x + threadIdx.x; i < total;
         i += (size_t)gridDim.x * blockDim.x) {
        float w = W[i];
        __half h = __float2half_rn(w);
        hi[i] = h;
        lo[i] = __float2half_rn(w - __half2float(h));
    }
}
__global__ void pack_w2(const float* __restrict__ W, size_t total,
                        __half* __restrict__ hi) {
    for (size_t i = (size_t)blockIdx.x * blockDim.x + threadIdx.x; i < total;
         i += (size_t)gridDim.x * blockDim.x)
        hi[i] = __float2half_rn(W[i]);
}

__global__ void fq_input(const float* __restrict__ x, const int* __restrict__ ridx) {
    int m = blockIdx.x;
    const float* xr = x + (size_t)m * DD;
    __shared__ float red[4];
    float amax = 0.f;
    for (int d = threadIdx.x; d < DD; d += 128) amax = fmaxf(amax, fabsf(xr[ridx[d]]));
    #pragma unroll
    for (int o = 16; o; o >>= 1) amax = fmaxf(amax, __shfl_xor_sync(~0u, amax, o));
    if ((threadIdx.x & 31) == 0) red[threadIdx.x >> 5] = amax;
    __syncthreads();
    amax = fmaxf(fmaxf(red[0], red[1]), fmaxf(red[2], red[3]));
    float s = fmaxf(amax / 127.0f, 1e-8f);
    if (threadIdx.x == 0) g_sx[m] = s;
    __half* orow = g_aq1 + (size_t)m * DD;
    for (int p = threadIdx.x; p < DD / 2; p += 128) {
        float q0 = fminf(fmaxf(rintf(xr[ridx[2*p]]   / s), -128.f), 127.f);
        float q1 = fminf(fmaxf(rintf(xr[ridx[2*p+1]] / s), -128.f), 127.f);
        *(__half2*)(orow + 2*p) = __floats2half2_rn(q0, q1);
    }
}

__global__ void quantize_h() {
    int m = blockIdx.x;
    float s = fmaxf(__uint_as_float(g_amax[m]) / 127.0f, 1e-8f);
    if (threadIdx.x == 0) g_s2[m] = s;
    const float* hr = g_h + (size_t)m * HH;
    __half* orow = g_aq2 + (size_t)m * HH;
    for (int p = threadIdx.x; p < HH / 4; p += 256) {
        float4 v = *(const float4*)(hr + 4*p);
        float q0 = fminf(fmaxf(rintf(v.x / s), -128.f), 127.f);
        float q1 = fminf(fmaxf(rintf(v.y / s), -128.f), 127.f);
        float q2 = fminf(fmaxf(rintf(v.z / s), -128.f), 127.f);
        float q3 = fminf(fmaxf(rintf(v.w / s), -128.f), 127.f);
        *(__half2*)(orow + 4*p)     = __floats2half2_rn(q0, q1);
        *(__half2*)(orow + 4*p + 2) = __floats2half2_rn(q2, q3);
    }
}

// ---------------------------------------------------------------------------
// GEMM1: hi-pass f32-acc + lo-pass f16-acc. CTA 128x128, BK=64, 2-stage
// cp.async, 2 CTAs/SM, 8 warps (4m x 2n), warp tile 32x64.
// NO kk rotation (R16 measured it hurts the two-plane loop).
// ---------------------------------------------------------------------------
__global__ void __launch_bounds__(256, 2)
gemm1_mma(const __half* __restrict__ A, const __half* __restrict__ Bh,
          const __half* __restrict__ Bl, const float* __restrict__ bias,
          const float* __restrict__ rowscale, float* __restrict__ C,
          int ldc, int K, unsigned* __restrict__ amaxU)
{
    constexpr uint32_t STAGE = 49152u;   // A16K | Bh16K | Bl16K
    extern __shared__ char smem[];
    const uint32_t sb = smem_u32(smem);
    const int tid = threadIdx.x;
    const int wid = tid >> 5, lane = tid & 31;
    const int wm = wid & 3, wn = wid >> 2;     // 4 (m) x 2 (n)
    const int bm = blockIdx.y * 128, bn = blockIdx.x * 128;
    const int nk = K >> 6;

    const int lr = lane & 15, lc = lane >> 4;
    const uint32_t aoff0 = swz((uint32_t)((wm * 32 + lr) * 128 + lc * 16));
    const uint32_t boff0 = swz((uint32_t)((wn * 64 + lr) * 128 + lc * 16));

    float acc[2][8][4];
    uint32_t acc16[2][8][2];
    #pragma unroll
    for (int i = 0; i < 2; i++)
        #pragma unroll
        for (int j = 0; j < 8; j++) {
            #pragma unroll
            for (int l = 0; l < 4; l++) acc[i][j][l] = 0.f;
            acc16[i][j][0] = 0u; acc16[i][j][1] = 0u;
        }

    const uint32_t fd0 = swz((uint32_t)((tid >> 3) * 128 + (tid & 7) * 16));
    const size_t   fs0 = (size_t)(tid >> 3) * K + (tid & 7) * 8;
    const __half* fA  = A  + (size_t)bm * K + fs0;
    const __half* fBh = Bh + (size_t)bn * K + fs0;
    const __half* fBl = Bl + (size_t)bn * K + fs0;
    const size_t rstep = (size_t)32 * K;

    auto fill = [&](int s, int k0) {
        uint32_t st = sb + (uint32_t)s * STAGE + fd0;
        #pragma unroll
        for (int r = 0; r < 4; r++) {
            cpa16(st + r * 4096u,            fA  + r * rstep + k0);
            cpa16(st + 16384u + r * 4096u,   fBh + r * rstep + k0);
            cpa16(st + 32768u + r * 4096u,   fBl + r * rstep + k0);
        }
    };

    fill(0, 0);  CP_COMMIT();
    if (nk > 1) fill(1, 64);
    CP_COMMIT();

    for (int ks = 0; ks < nk; ks++) {
        CP_WAIT1();
        __syncthreads();
        const uint32_t st = sb + (uint32_t)(ks & 1) * STAGE;

        #pragma unroll
        for (int kk = 0; kk < 4; kk++) {
            const uint32_t kx = (uint32_t)(kk * 32);
            const uint32_t ab = st + (aoff0 ^ kx);
            const uint32_t bbse = st + (boff0 ^ kx);
            uint32_t a[2][4], b[2][4];
            ldm4(a[0], ab);
            ldm4(a[1], ab + 2048u);
            // ---- hi plane: f32 accumulate ----
            ldm4(b[0], bbse + 16384u);
            ldm4(b[1], bbse + 16384u + 2048u);
            #pragma unroll
            for (int mt = 0; mt < 2; mt++) {
                mma16816(acc[mt][0], a[mt], b[0][0], b[0][2]);
                mma16816(acc[mt][1], a[mt], b[0][1], b[0][3]);
                mma16816(acc[mt][2], a[mt], b[1][0], b[1][2]);
                mma16816(acc[mt][3], a[mt], b[1][1], b[1][3]);
            }
            ldm4(b[0], bbse + 16384u + 4096u);
            ldm4(b[1], bbse + 16384u + 6144u);
            #pragma unroll
            for (int mt = 0; mt < 2; mt++) {
                mma16816(acc[mt][4], a[mt], b[0][0], b[0][2]);
                mma16816(acc[mt][5], a[mt], b[0][1], b[0][3]);
                mma16816(acc[mt][6], a[mt], b[1][0], b[1][2]);
                mma16816(acc[mt][7], a[mt], b[1][1], b[1][3]);
            }
            // ---- lo plane: f16 accumulate ----
            ldm4(b[0], bbse + 32768u);
            ldm4(b[1], bbse + 32768u + 2048u);
            #pragma unroll
            for (int mt = 0; mt < 2; mt++) {
                mma16816h(acc16[mt][0], a[mt], b[0][0], b[0][2]);
                mma16816h(acc16[mt][1], a[mt], b[0][1], b[0][3]);
                mma16816h(acc16[mt][2], a[mt], b[1][0], b[1][2]);
                mma16816h(acc16[mt][3], a[mt], b[1][1], b[1][3]);
            }
            ldm4(b[0], bbse + 32768u + 4096u);
            ldm4(b[1], bbse + 32768u + 6144u);
            #pragma unroll
            for (int mt = 0; mt < 2; mt++) {
                mma16816h(acc16[mt][4], a[mt], b[0][0], b[0][2]);
                mma16816h(acc16[mt][5], a[mt], b[0][1], b[0][3]);
                mma16816h(acc16[mt][6], a[mt], b[1][0], b[1][2]);
                mma16816h(acc16[mt][7], a[mt], b[1][1], b[1][3]);
            }
        }

        __syncthreads();
        if (ks + 2 < nk) fill(ks & 1, (ks + 2) * 64);
        CP_COMMIT();
    }

    // ---- epilogue: combine hi+lo, bias + GELU + store + row absmax ----
    const int q = lane >> 2, c2 = (lane & 3) * 2;
    #pragma unroll
    for (int mt = 0; mt < 2; mt++) {
        int r0 = bm + wm * 32 + mt * 16 + q;
        float rs0 = rowscale[r0], rs1 = rowscale[r0 + 8];
        float mx0 = 0.f, mx1 = 0.f;
        #pragma unroll
        for (int nt = 0; nt < 8; nt++) {
            int col = bn + wn * 64 + nt * 8 + c2;
            float2 bb = *(const float2*)(bias + col);
            float2 l0 = __half22float2(*(__half2*)&acc16[mt][nt][0]);
            float2 l1 = __half22float2(*(__half2*)&acc16[mt][nt][1]);
            float v0 = gelu_exact((acc[mt][nt][0] + l0.x) * rs0 + bb.x);
            float v1 = gelu_exact((acc[mt][nt][1] + l0.y) * rs0 + bb.y);
            float v2 = gelu_exact((acc[mt][nt][2] + l1.x) * rs1 + bb.x);
            float v3 = gelu_exact((acc[mt][nt][3] + l1.y) * rs1 + bb.y);
            mx0 = fmaxf(mx0, fmaxf(fabsf(v0), fabsf(v1)));
            mx1 = fmaxf(mx1, fmaxf(fabsf(v2), fabsf(v3)));
            float2 o0 = {v0, v1}, o1 = {v2, v3};
            *(float2*)(C + (size_t)r0 * ldc + col) = o0;
            *(float2*)(C + (size_t)(r0 + 8) * ldc + col) = o1;
        }
        mx0 = fmaxf(mx0, __shfl_xor_sync(~0u, mx0, 1));
        mx0 = fmaxf(mx0, __shfl_xor_sync(~0u, mx0, 2));
        mx1 = fmaxf(mx1, __shfl_xor_sync(~0u, mx1, 1));
        mx1 = fmaxf(mx1, __shfl_xor_sync(~0u, mx1, 2));
        if ((lane & 3) == 0) {
            atomicMax(amaxU + r0,     __float_as_uint(mx0));
            atomicMax(amaxU + r0 + 8, __float_as_uint(mx1));
        }
    }
}

// ---------------------------------------------------------------------------
// GEMM2 (hi only): CTA 128x128, BK=64, 3-stage ring, single barrier/k-step,
// 8 warps (4m x 2n), warp tile 32x64, 2 CTAs/SM. Warp-rotated kk order (R16 win).
// ---------------------------------------------------------------------------
__global__ void __launch_bounds__(256, 2)
gemm2_mma(const __half* __restrict__ A, const __half* __restrict__ Bh,
          const float* __restrict__ bias, const float* __restrict__ rowscale,
          float* __restrict__ C, int ldc, int K)
{
    constexpr uint32_t STAGE = 32768u;   // A16K | Bh16K
    extern __shared__ char smem[];
    const uint32_t sb = smem_u32(smem);
    const int tid = threadIdx.x;
    const int wid = tid >> 5, lane = tid & 31;
    const int wm = wid & 3, wn = wid >> 2;
    const int bm = blockIdx.y * 128, bn = blockIdx.x * 128;
    const int nk = K >> 6;

    const int lr = lane & 15, lc = lane >> 4;
    uint32_t aoff[2], boff[4];
    #pragma unroll
    for (int mt = 0; mt < 2; mt++)
        aoff[mt] = swz((uint32_t)((wm * 32 + mt * 16 + lr) * 128 + lc * 16));
    #pragma unroll
    for (int g = 0; g < 4; g++)
        boff[g] = 16384u + swz((uint32_t)((wn * 64 + g * 16 + lr) * 128 + lc * 16));

    float acc[2][8][4];
    #pragma unroll
    for (int i = 0; i < 2; i++)
        #pragma unroll
        for (int j = 0; j < 8; j++)
            #pragma unroll
            for (int l = 0; l < 4; l++) acc[i][j][l] = 0.f;

    const uint32_t fd0 = swz((uint32_t)((tid >> 3) * 128 + (tid & 7) * 16));
    const size_t   fs0 = (size_t)(tid >> 3) * K + (tid & 7) * 8;
    const __half* fA  = A  + (size_t)bm * K + fs0;
    const __half* fBh = Bh + (size_t)bn * K + fs0;
    const size_t rstep = (size_t)32 * K;

    auto fill = [&](int s, int k0) {
        uint32_t st = sb + (uint32_t)s * STAGE + fd0;
        #pragma unroll
        for (int r = 0; r < 4; r++) {
            cpa16(st + r * 4096u,          fA  + r * rstep + k0);
            cpa16(st + 16384u + r * 4096u, fBh + r * rstep + k0);
        }
    };

    fill(0, 0);  CP_COMMIT();
    fill(1, 64); CP_COMMIT();

    int stage = 0;
    for (int ks = 0; ks < nk; ks++) {
        CP_WAIT1();
        __syncthreads();
        if (ks + 2 < nk) {
            int ts = stage + 2; if (ts >= 3) ts -= 3;
            fill(ts, (ks + 2) * 64);
        }
        CP_COMMIT();

        const uint32_t st = sb + (uint32_t)stage * STAGE;
        #pragma unroll
        for (int kk = 0; kk < 4; kk++) {
            const uint32_t kx = (uint32_t)(((kk + wid) & 3) * 32);
            uint32_t a[2][4], b[4][4];
            #pragma unroll
            for (int mt = 0; mt < 2; mt++) ldm4(a[mt], st + (aoff[mt] ^ kx));
            #pragma unroll
            for (int g = 0; g < 4; g++) ldm4(b[g], st + (boff[g] ^ kx));
            #pragma unroll
            for (int mt = 0; mt < 2; mt++)
                #pragma unroll
                for (int g = 0; g < 4; g++) {
                    mma16816(acc[mt][2*g],   a[mt], b[g][0], b[g][2]);
                    mma16816(acc[mt][2*g+1], a[mt], b[g][1], b[g][3]);
                }
        }
        if (++stage == 3) stage = 0;
    }

    const int q = lane >> 2, c2 = (lane & 3) * 2;
    #pragma unroll
    for (int mt = 0; mt < 2; mt++) {
        int r0 = bm + wm * 32 + mt * 16 + q;
        float rs0 = rowscale[r0], rs1 = rowscale[r0 + 8];
        #pragma unroll
        for (int nt = 0; nt < 8; nt++) {
            int col = bn + wn * 64 + nt * 8 + c2;
            float2 bb = *(const float2*)(bias + col);
            float2 o0 = {acc[mt][nt][0] * rs0 + bb.x, acc[mt][nt][1] * rs0 + bb.y};
            float2 o1 = {acc[mt][nt][2] * rs1 + bb.x, acc[mt][nt][3] * rs1 + bb.y};
            *(float2*)(C + (size_t)r0 * ldc + col) = o0;
            *(float2*)(C + (size_t)(r0 + 8) * ldc + col) = o1;
        }
    }
}

// ---------------------------------------------------------------------------
extern "C" void kernel_launch(void* const* d_in, const int* in_sizes, int n_in,
                              void* d_out, int out_size) {
    const float* x   = (const float*)d_in[0];
    const int*   idx = (const int*)d_in[1];
    const float* W1  = (const float*)d_in[2];
    const float* b1  = (const float*)d_in[3];
    const float* W2  = (const float*)d_in[4];
    const float* b2  = (const float*)d_in[5];
    float* out = (float*)d_out;

    void *aq1, *aq2, *hptr, *w1h, *w1l, *w2h, *sx, *s2, *am;
    cudaGetSymbolAddress(&aq1, g_aq1);  cudaGetSymbolAddress(&aq2, g_aq2);
    cudaGetSymbolAddress(&hptr, g_h);
    cudaGetSymbolAddress(&w1h, g_w1hi); cudaGetSymbolAddress(&w1l, g_w1lo);
    cudaGetSymbolAddress(&w2h, g_w2hi);
    cudaGetSymbolAddress(&sx, g_sx);    cudaGetSymbolAddress(&s2, g_s2);
    cudaGetSymbolAddress(&am, g_amax);

    const int SMEM1 = 2 * 49152;   // 96KB -> 2 CTAs/SM
    const int SMEM2 = 3 * 32768;   // 96KB -> 2 CTAs/SM
    cudaFuncSetAttribute((const void*)gemm1_mma, cudaFuncAttributeMaxDynamicSharedMemorySize, SMEM1);
    cudaFuncSetAttribute((const void*)gemm2_mma, cudaFuncAttributeMaxDynamicSharedMemorySize, SMEM2);

    pack_w1<<<2048, 256>>>(W1, (size_t)HH * DD, (__half*)w1h, (__half*)w1l);
    pack_w2<<<2048, 256>>>(W2, (size_t)DD * HH, (__half*)w2h);
    cudaMemsetAsync(am, 0, MM * sizeof(unsigned));
    fq_input<<<MM, 128>>>(x, idx);

    gemm1_mma<<<dim3(HH / 128, MM / 128), 256, SMEM1>>>(
        (const __half*)aq1, (const __half*)w1h, (const __half*)w1l,
        b1, (const float*)sx, (float*)hptr, HH, DD, (unsigned*)am);

    quantize_h<<<MM, 256>>>();

    gemm2_mma<<<dim3(DD / 128, MM / 128), 256, SMEM2>>>(
        (const __half*)aq2, (const __half*)w2h,
        b2, (const float*)s2, out, DD, HH);
}